// round 2
// baseline (speedup 1.0000x reference)
#include <cuda_runtime.h>
#include <math.h>

#define ROWS 16
#define NTHR 256

__device__ __forceinline__ float siluf(float x) {
    return x / (1.0f + __expf(-x));
}

// Exact Plackett-Luce log-prob of an unordered 5-set via subset DP.
// e[q] = exp(l_sel[q] - m), S = sum of selected logits, Z = sum exp(l - m) over all 64.
// lp = S - 5m + log( sum over 120 orderings of prod_t 1/Z_t ), Z_t scaled by exp(-m).
__device__ __forceinline__ float pl_lp(const float e[5], float S, float m, float Z) {
    float g[32];
    float sE[32];
    g[0] = 1.0f;
    sE[0] = 0.0f;
#pragma unroll
    for (int mask = 1; mask < 32; ++mask) {
        float se = 0.0f;
        float acc = 0.0f;
#pragma unroll
        for (int i = 0; i < 5; ++i) {
            if (mask & (1 << i)) {
                int sub = mask ^ (1 << i);
                se += e[i];
                acc += g[sub] * __fdividef(1.0f, Z - sE[sub]);
            }
        }
        sE[mask] = se;
        g[mask] = acc;
    }
    return S - 5.0f * m + logf(g[31]);
}

// Warp-collective top-5 over 64 values (2 per lane: indices lane, lane+32).
// Tie-break: smaller index wins (matches jax.lax.top_k).
__device__ __forceinline__ void warp_top5(float v0, float v1, int lane, int sel[5]) {
    int i0 = lane, i1 = lane + 32;
#pragma unroll
    for (int q = 0; q < 5; ++q) {
        float bv; int bi;
        if (v0 > v1 || (v0 == v1 && i0 < i1)) { bv = v0; bi = i0; }
        else { bv = v1; bi = i1; }
#pragma unroll
        for (int off = 16; off > 0; off >>= 1) {
            float ov = __shfl_xor_sync(0xffffffffu, bv, off);
            int   oi = __shfl_xor_sync(0xffffffffu, bi, off);
            if (ov > bv || (ov == bv && oi < bi)) { bv = ov; bi = oi; }
        }
        sel[q] = bi;
        if (bi == i0) v0 = -INFINITY;
        if (bi == i1) v1 = -INFINITY;
    }
}

__global__ void __launch_bounds__(NTHR) pcf_kernel(
    const float* __restrict__ uA, const float* __restrict__ uB,
    const float* __restrict__ aLog,
    const float* __restrict__ W1, const float* __restrict__ b1,
    const float* __restrict__ W2, const float* __restrict__ b2,
    const float* __restrict__ V1, const float* __restrict__ c1,
    const float* __restrict__ V2, const float* __restrict__ c2,
    const float* __restrict__ V3, const float* __restrict__ c3,
    float* __restrict__ out, int Btot)
{
    __shared__ float sAL[64];
    __shared__ float sExpA[64];
    __shared__ float sMZ[2];          // m_a, Z_a
    __shared__ int   sSelA[ROWS][5];
    __shared__ int   sSelB[ROWS][5];
    __shared__ __align__(16) float bufA[ROWS * 256]; // H [16][128] then Z2 [16][256]
    __shared__ __align__(16) float bufB[ROWS * 256]; // Z1 [16][256]
    __shared__ __align__(16) float bufC[ROWS * 64];  // Ctx [16][64] then BL [16][64]

    const int t = threadIdx.x;
    const int lane = t & 31;
    const int warp = t >> 5;
    const int b0 = blockIdx.x * ROWS;

    if (t < 64) sAL[t] = aLog[t];
    __syncthreads();

    // ---- P1: alpha softmax stats (warp 0) + alpha gumbel top-5 (all warps) ----
    if (warp == 0) {
        float l0 = sAL[lane], l1 = sAL[lane + 32];
        float m = fmaxf(l0, l1);
#pragma unroll
        for (int off = 16; off; off >>= 1) m = fmaxf(m, __shfl_xor_sync(0xffffffffu, m, off));
        float e0 = __expf(l0 - m), e1 = __expf(l1 - m);
        sExpA[lane] = e0; sExpA[lane + 32] = e1;
        float z = e0 + e1;
#pragma unroll
        for (int off = 16; off; off >>= 1) z += __shfl_xor_sync(0xffffffffu, z, off);
        if (lane == 0) { sMZ[0] = m; sMZ[1] = z; }
    }
    {
        float l0 = sAL[lane], l1 = sAL[lane + 32];
#pragma unroll
        for (int k = 0; k < 2; ++k) {
            int r = warp * 2 + k;
            int b = b0 + r;
            float u0 = uA[b * 64 + lane];
            float u1 = uA[b * 64 + lane + 32];
            float p0 = l0 - logf(-logf(fmaxf(u0, 1e-10f)));
            float p1 = l1 - logf(-logf(fmaxf(u1, 1e-10f)));
            int sel[5];
            warp_top5(p0, p1, lane, sel);
            if (lane == 0) {
                sSelA[r][0] = sel[0]; sSelA[r][1] = sel[1]; sSelA[r][2] = sel[2];
                sSelA[r][3] = sel[3]; sSelA[r][4] = sel[4];
            }
        }
    }
    __syncthreads();

    // ---- P2: h = silu(gather-sum of 5 W1 rows + b1)  [16][128] ----
    {
        float (*sH)[128] = (float(*)[128])bufA;
#pragma unroll
        for (int e = 0; e < 8; ++e) {
            int idx = t + NTHR * e;
            int r = idx >> 7, j = idx & 127;
            const int* sel = sSelA[r];
            float s = b1[j];
#pragma unroll
            for (int q = 0; q < 5; ++q) s += W1[sel[q] * 128 + j];
            sH[r][j] = siluf(s);
        }
    }
    __syncthreads();

    // ---- P3: ctx = h @ W2 + b2   [16][64] ----
    {
        float (*sH)[128] = (float(*)[128])bufA;
        float (*sCtx)[64] = (float(*)[64])bufC;
#pragma unroll
        for (int e = 0; e < 4; ++e) {
            int idx = t + NTHR * e;
            int r = idx >> 6, j = idx & 63;
            const float4* h4 = (const float4*)sH[r];
            float s = b2[j];
#pragma unroll 8
            for (int c = 0; c < 32; ++c) {
                float4 hv = h4[c];
                s += hv.x * W2[(4 * c + 0) * 64 + j];
                s += hv.y * W2[(4 * c + 1) * 64 + j];
                s += hv.z * W2[(4 * c + 2) * 64 + j];
                s += hv.w * W2[(4 * c + 3) * 64 + j];
            }
            sCtx[r][j] = s;
        }
    }
    __syncthreads();

    // ---- P4: z1 = silu(ctx @ V1[64:,:] + c1)   [16][256] ----
    {
        float (*sCtx)[64] = (float(*)[64])bufC;
        float (*sZ1)[256] = (float(*)[256])bufB;
        int j = t;  // column 0..255
        float acc[ROWS];
        float cj = c1[j];
#pragma unroll
        for (int r = 0; r < ROWS; ++r) acc[r] = cj;
#pragma unroll 4
        for (int c = 0; c < 16; ++c) {
            float w0 = V1[(64 + 4 * c + 0) * 256 + j];
            float w1 = V1[(64 + 4 * c + 1) * 256 + j];
            float w2v = V1[(64 + 4 * c + 2) * 256 + j];
            float w3 = V1[(64 + 4 * c + 3) * 256 + j];
#pragma unroll
            for (int r = 0; r < ROWS; ++r) {
                float4 cv = ((const float4*)sCtx[r])[c];
                acc[r] += cv.x * w0 + cv.y * w1 + cv.z * w2v + cv.w * w3;
            }
        }
#pragma unroll
        for (int r = 0; r < ROWS; ++r) sZ1[r][j] = siluf(acc[r]);
    }
    __syncthreads();

    // ---- P5: z2 = silu(z1 @ V2 + c2)   [16][256]  (dominant matmul) ----
    {
        float (*sZ1)[256] = (float(*)[256])bufB;
        float (*sZ2)[256] = (float(*)[256])bufA;
        int j = t;
        float acc[ROWS];
        float cj = c2[j];
#pragma unroll
        for (int r = 0; r < ROWS; ++r) acc[r] = cj;
#pragma unroll 2
        for (int c = 0; c < 64; ++c) {
            float w0 = V2[(4 * c + 0) * 256 + j];
            float w1 = V2[(4 * c + 1) * 256 + j];
            float w2v = V2[(4 * c + 2) * 256 + j];
            float w3 = V2[(4 * c + 3) * 256 + j];
#pragma unroll
            for (int r = 0; r < ROWS; ++r) {
                float4 zv = ((const float4*)sZ1[r])[c];
                acc[r] += zv.x * w0 + zv.y * w1 + zv.z * w2v + zv.w * w3;
            }
        }
#pragma unroll
        for (int r = 0; r < ROWS; ++r) sZ2[r][j] = siluf(acc[r]);
    }
    __syncthreads();

    // ---- P6: beta_logits = z2 @ V3 + c3   [16][64] ----
    {
        float (*sZ2)[256] = (float(*)[256])bufA;
        float (*sBL)[64] = (float(*)[64])bufC;
#pragma unroll
        for (int e = 0; e < 4; ++e) {
            int idx = t + NTHR * e;
            int r = idx >> 6, j = idx & 63;
            const float4* z4 = (const float4*)sZ2[r];
            float s = c3[j];
#pragma unroll 8
            for (int c = 0; c < 64; ++c) {
                float4 zv = z4[c];
                s += zv.x * V3[(4 * c + 0) * 64 + j];
                s += zv.y * V3[(4 * c + 1) * 64 + j];
                s += zv.z * V3[(4 * c + 2) * 64 + j];
                s += zv.w * V3[(4 * c + 3) * 64 + j];
            }
            sBL[r][j] = s;
        }
    }
    __syncthreads();

    // ---- P7: beta gumbel top-5 + both PL log-probs ----
    {
        float (*sBL)[64] = (float(*)[64])bufC;
        float mA = sMZ[0], zA = sMZ[1];
#pragma unroll
        for (int k = 0; k < 2; ++k) {
            int r = warp * 2 + k;
            int b = b0 + r;
            float l0 = sBL[r][lane], l1 = sBL[r][lane + 32];
            float u0 = uB[b * 64 + lane];
            float u1 = uB[b * 64 + lane + 32];
            float p0 = l0 - logf(-logf(fmaxf(u0, 1e-10f)));
            float p1 = l1 - logf(-logf(fmaxf(u1, 1e-10f)));
            int sel[5];
            warp_top5(p0, p1, lane, sel);
            // softmax stats over beta logits (not perturbed)
            float m = fmaxf(l0, l1);
#pragma unroll
            for (int off = 16; off; off >>= 1) m = fmaxf(m, __shfl_xor_sync(0xffffffffu, m, off));
            float z = __expf(l0 - m) + __expf(l1 - m);
#pragma unroll
            for (int off = 16; off; off >>= 1) z += __shfl_xor_sync(0xffffffffu, z, off);
            if (lane == 0) {
                sSelB[r][0] = sel[0]; sSelB[r][1] = sel[1]; sSelB[r][2] = sel[2];
                sSelB[r][3] = sel[3]; sSelB[r][4] = sel[4];
                float eb[5], Sb = 0.0f;
#pragma unroll
                for (int q = 0; q < 5; ++q) {
                    float lv = sBL[r][sel[q]];
                    Sb += lv;
                    eb[q] = __expf(lv - m);
                }
                float lpb = pl_lp(eb, Sb, m, z);
                float ea[5], Sa = 0.0f;
#pragma unroll
                for (int q = 0; q < 5; ++q) {
                    int ia = sSelA[r][q];
                    Sa += sAL[ia];
                    ea[q] = sExpA[ia];
                }
                float lpa = pl_lp(ea, Sa, mA, zA);
                out[Btot * 128 + b] = lpa + lpb;
            }
        }
    }
    __syncthreads();

    // ---- P8: write configs (0/1 masks) ----
    {
#pragma unroll
        for (int e = 0; e < 8; ++e) {
            int idx = t + NTHR * e;
            int r = idx >> 7, j = idx & 127;
            int b = b0 + r;
            float v;
            if (j < 64) {
                const int* s = sSelA[r];
                v = (j == s[0] || j == s[1] || j == s[2] || j == s[3] || j == s[4]) ? 1.0f : 0.0f;
            } else {
                int jj = j - 64;
                const int* s = sSelB[r];
                v = (jj == s[0] || jj == s[1] || jj == s[2] || jj == s[3] || jj == s[4]) ? 1.0f : 0.0f;
            }
            out[b * 128 + j] = v;
        }
    }
}

extern "C" void kernel_launch(void* const* d_in, const int* in_sizes, int n_in,
                              void* d_out, int out_size) {
    const float* uA = (const float*)d_in[0];
    const float* uB = (const float*)d_in[1];
    const float* aL = (const float*)d_in[2];
    const float* W1 = (const float*)d_in[3];
    const float* b1 = (const float*)d_in[4];
    const float* W2 = (const float*)d_in[5];
    const float* b2 = (const float*)d_in[6];
    const float* V1 = (const float*)d_in[7];
    const float* c1 = (const float*)d_in[8];
    const float* V2 = (const float*)d_in[9];
    const float* c2 = (const float*)d_in[10];
    const float* V3 = (const float*)d_in[11];
    const float* c3 = (const float*)d_in[12];
    int B = in_sizes[0] / 64;
    int grid = B / ROWS;
    pcf_kernel<<<grid, NTHR>>>(uA, uB, aL, W1, b1, W2, b2,
                               V1, c1, V2, c2, V3, c3,
                               (float*)d_out, B);
}

// round 3
// speedup vs baseline: 1.2462x; 1.2462x over previous
#include <cuda_runtime.h>
#include <math.h>

#define ROWS 16
#define NTHR 256

__device__ __forceinline__ float siluf(float x) {
    return x / (1.0f + __expf(-x));
}

// Exact Plackett-Luce log-prob of an unordered 5-set via subset DP.
__device__ __forceinline__ float pl_lp(const float e[5], float S, float m, float Z) {
    float g[32];
    float sE[32];
    g[0] = 1.0f;
    sE[0] = 0.0f;
#pragma unroll
    for (int mask = 1; mask < 32; ++mask) {
        float se = 0.0f;
        float acc = 0.0f;
#pragma unroll
        for (int i = 0; i < 5; ++i) {
            if (mask & (1 << i)) {
                int sub = mask ^ (1 << i);
                se += e[i];
                acc += g[sub] * __fdividef(1.0f, Z - sE[sub]);
            }
        }
        sE[mask] = se;
        g[mask] = acc;
    }
    return S - 5.0f * m + logf(g[31]);
}

// Warp-collective top-5 over 64 values (2 per lane). Tie-break: smaller index.
__device__ __forceinline__ void warp_top5(float v0, float v1, int lane, int sel[5]) {
    int i0 = lane, i1 = lane + 32;
#pragma unroll
    for (int q = 0; q < 5; ++q) {
        float bv; int bi;
        if (v0 > v1 || (v0 == v1 && i0 < i1)) { bv = v0; bi = i0; }
        else { bv = v1; bi = i1; }
#pragma unroll
        for (int off = 16; off > 0; off >>= 1) {
            float ov = __shfl_xor_sync(0xffffffffu, bv, off);
            int   oi = __shfl_xor_sync(0xffffffffu, bi, off);
            if (ov > bv || (ov == bv && oi < bi)) { bv = ov; bi = oi; }
        }
        sel[q] = bi;
        if (bi == i0) v0 = -INFINITY;
        if (bi == i1) v1 = -INFINITY;
    }
}

__global__ void __launch_bounds__(NTHR) pcf_kernel(
    const float* __restrict__ uA, const float* __restrict__ uB,
    const float* __restrict__ aLog,
    const float* __restrict__ W1, const float* __restrict__ b1,
    const float* __restrict__ W2, const float* __restrict__ b2,
    const float* __restrict__ V1, const float* __restrict__ c1,
    const float* __restrict__ V2, const float* __restrict__ c2,
    const float* __restrict__ V3, const float* __restrict__ c3,
    float* __restrict__ out, int Btot)
{
    __shared__ float sAL[64];
    __shared__ float sExpA[64];
    __shared__ float sMZ[2];
    __shared__ int   sSelA[ROWS][5];
    __shared__ int   sSelB[ROWS][5];
    __shared__ __align__(16) float bufA[ROWS * 256]; // H [16][128] then Z2 [16][256]
    __shared__ __align__(16) float bufB[ROWS * 256]; // Z1 [16][256]
    __shared__ __align__(16) float bufC[ROWS * 64];  // Ctx [16][64] then BL [16][64]

    const int t = threadIdx.x;
    const int lane = t & 31;
    const int warp = t >> 5;
    const int b0 = blockIdx.x * ROWS;

    if (t < 64) sAL[t] = aLog[t];
    __syncthreads();

    // ---- P1: alpha softmax stats (warp 0) + alpha gumbel top-5 (all warps) ----
    if (warp == 0) {
        float l0 = sAL[lane], l1 = sAL[lane + 32];
        float m = fmaxf(l0, l1);
#pragma unroll
        for (int off = 16; off; off >>= 1) m = fmaxf(m, __shfl_xor_sync(0xffffffffu, m, off));
        float e0 = __expf(l0 - m), e1 = __expf(l1 - m);
        sExpA[lane] = e0; sExpA[lane + 32] = e1;
        float z = e0 + e1;
#pragma unroll
        for (int off = 16; off; off >>= 1) z += __shfl_xor_sync(0xffffffffu, z, off);
        if (lane == 0) { sMZ[0] = m; sMZ[1] = z; }
    }
    {
        float l0 = sAL[lane], l1 = sAL[lane + 32];
#pragma unroll
        for (int k = 0; k < 2; ++k) {
            int r = warp * 2 + k;
            int b = b0 + r;
            float u0 = uA[b * 64 + lane];
            float u1 = uA[b * 64 + lane + 32];
            float p0 = l0 - logf(-logf(fmaxf(u0, 1e-10f)));
            float p1 = l1 - logf(-logf(fmaxf(u1, 1e-10f)));
            int sel[5];
            warp_top5(p0, p1, lane, sel);
            if (lane == 0) {
                sSelA[r][0] = sel[0]; sSelA[r][1] = sel[1]; sSelA[r][2] = sel[2];
                sSelA[r][3] = sel[3]; sSelA[r][4] = sel[4];
            }
        }
    }
    __syncthreads();

    // ---- P2: h = silu(gather-sum of 5 W1 rows + b1)  [16][128] ----
    {
        float (*sH)[128] = (float(*)[128])bufA;
#pragma unroll
        for (int e = 0; e < 8; ++e) {
            int idx = t + NTHR * e;
            int r = idx >> 7, j = idx & 127;
            const int* sel = sSelA[r];
            float s = b1[j];
#pragma unroll
            for (int q = 0; q < 5; ++q) s += W1[sel[q] * 128 + j];
            sH[r][j] = siluf(s);
        }
    }
    __syncthreads();

    // ---- P3: ctx = h @ W2 + b2   [16][64]  (4 rows x 1 col per thread) ----
    {
        float (*sH)[128] = (float(*)[128])bufA;
        float (*sCtx)[64] = (float(*)[64])bufC;
        const int j = t & 63;
        const int r0 = (t >> 6) * 4;
        float acc0 = b2[j], acc1 = acc0, acc2 = acc0, acc3 = acc0;
#pragma unroll 4
        for (int kc = 0; kc < 32; ++kc) {
            float w0 = W2[(kc * 4 + 0) * 64 + j];
            float w1 = W2[(kc * 4 + 1) * 64 + j];
            float w2v = W2[(kc * 4 + 2) * 64 + j];
            float w3 = W2[(kc * 4 + 3) * 64 + j];
            float4 h0 = *(const float4*)&sH[r0 + 0][kc * 4];
            float4 h1 = *(const float4*)&sH[r0 + 1][kc * 4];
            float4 h2 = *(const float4*)&sH[r0 + 2][kc * 4];
            float4 h3 = *(const float4*)&sH[r0 + 3][kc * 4];
            acc0 += h0.x * w0 + h0.y * w1 + h0.z * w2v + h0.w * w3;
            acc1 += h1.x * w0 + h1.y * w1 + h1.z * w2v + h1.w * w3;
            acc2 += h2.x * w0 + h2.y * w1 + h2.z * w2v + h2.w * w3;
            acc3 += h3.x * w0 + h3.y * w1 + h3.z * w2v + h3.w * w3;
        }
        sCtx[r0 + 0][j] = acc0;
        sCtx[r0 + 1][j] = acc1;
        sCtx[r0 + 2][j] = acc2;
        sCtx[r0 + 3][j] = acc3;
    }
    __syncthreads();

    // ---- P4: z1 = silu(ctx @ V1[64:,:] + c1)  [16][256]  (4x4 tile) ----
    {
        float (*sCtx)[64] = (float(*)[64])bufC;
        float (*sZ1)[256] = (float(*)[256])bufB;
        const int j0 = (t & 63) * 4;
        const int r0 = (t >> 6) * 4;
        float4 bias = *(const float4*)&c1[j0];
        float acc[4][4];
#pragma unroll
        for (int r = 0; r < 4; ++r) {
            acc[r][0] = bias.x; acc[r][1] = bias.y; acc[r][2] = bias.z; acc[r][3] = bias.w;
        }
#pragma unroll 4
        for (int kc = 0; kc < 16; ++kc) {
            float4 w[4];
#pragma unroll
            for (int i = 0; i < 4; ++i)
                w[i] = *(const float4*)&V1[(64 + kc * 4 + i) * 256 + j0];
            float4 z[4];
#pragma unroll
            for (int i = 0; i < 4; ++i)
                z[i] = *(const float4*)&sCtx[r0 + i][kc * 4];
#pragma unroll
            for (int r = 0; r < 4; ++r) {
                acc[r][0] += z[r].x * w[0].x + z[r].y * w[1].x + z[r].z * w[2].x + z[r].w * w[3].x;
                acc[r][1] += z[r].x * w[0].y + z[r].y * w[1].y + z[r].z * w[2].y + z[r].w * w[3].y;
                acc[r][2] += z[r].x * w[0].z + z[r].y * w[1].z + z[r].z * w[2].z + z[r].w * w[3].z;
                acc[r][3] += z[r].x * w[0].w + z[r].y * w[1].w + z[r].z * w[2].w + z[r].w * w[3].w;
            }
        }
#pragma unroll
        for (int r = 0; r < 4; ++r) {
            float4 o;
            o.x = siluf(acc[r][0]); o.y = siluf(acc[r][1]);
            o.z = siluf(acc[r][2]); o.w = siluf(acc[r][3]);
            *(float4*)&sZ1[r0 + r][j0] = o;
        }
    }
    __syncthreads();

    // ---- P5: z2 = silu(z1 @ V2 + c2)  [16][256]  (4x4 tile, dominant) ----
    {
        float (*sZ1)[256] = (float(*)[256])bufB;
        float (*sZ2)[256] = (float(*)[256])bufA;
        const int j0 = (t & 63) * 4;
        const int r0 = (t >> 6) * 4;
        float4 bias = *(const float4*)&c2[j0];
        float acc[4][4];
#pragma unroll
        for (int r = 0; r < 4; ++r) {
            acc[r][0] = bias.x; acc[r][1] = bias.y; acc[r][2] = bias.z; acc[r][3] = bias.w;
        }
#pragma unroll 4
        for (int kc = 0; kc < 64; ++kc) {
            float4 w[4];
#pragma unroll
            for (int i = 0; i < 4; ++i)
                w[i] = *(const float4*)&V2[(kc * 4 + i) * 256 + j0];
            float4 z[4];
#pragma unroll
            for (int i = 0; i < 4; ++i)
                z[i] = *(const float4*)&sZ1[r0 + i][kc * 4];
#pragma unroll
            for (int r = 0; r < 4; ++r) {
                acc[r][0] += z[r].x * w[0].x + z[r].y * w[1].x + z[r].z * w[2].x + z[r].w * w[3].x;
                acc[r][1] += z[r].x * w[0].y + z[r].y * w[1].y + z[r].z * w[2].y + z[r].w * w[3].y;
                acc[r][2] += z[r].x * w[0].z + z[r].y * w[1].z + z[r].z * w[2].z + z[r].w * w[3].z;
                acc[r][3] += z[r].x * w[0].w + z[r].y * w[1].w + z[r].z * w[2].w + z[r].w * w[3].w;
            }
        }
#pragma unroll
        for (int r = 0; r < 4; ++r) {
            float4 o;
            o.x = siluf(acc[r][0]); o.y = siluf(acc[r][1]);
            o.z = siluf(acc[r][2]); o.w = siluf(acc[r][3]);
            *(float4*)&sZ2[r0 + r][j0] = o;
        }
    }
    __syncthreads();

    // ---- P6: beta_logits = z2 @ V3 + c3  [16][64]  (4 rows x 1 col) ----
    {
        float (*sZ2)[256] = (float(*)[256])bufA;
        float (*sBL)[64] = (float(*)[64])bufC;
        const int j = t & 63;
        const int r0 = (t >> 6) * 4;
        float acc0 = c3[j], acc1 = acc0, acc2 = acc0, acc3 = acc0;
#pragma unroll 4
        for (int kc = 0; kc < 64; ++kc) {
            float w0 = V3[(kc * 4 + 0) * 64 + j];
            float w1 = V3[(kc * 4 + 1) * 64 + j];
            float w2v = V3[(kc * 4 + 2) * 64 + j];
            float w3 = V3[(kc * 4 + 3) * 64 + j];
            float4 z0 = *(const float4*)&sZ2[r0 + 0][kc * 4];
            float4 z1v = *(const float4*)&sZ2[r0 + 1][kc * 4];
            float4 z2v = *(const float4*)&sZ2[r0 + 2][kc * 4];
            float4 z3 = *(const float4*)&sZ2[r0 + 3][kc * 4];
            acc0 += z0.x * w0 + z0.y * w1 + z0.z * w2v + z0.w * w3;
            acc1 += z1v.x * w0 + z1v.y * w1 + z1v.z * w2v + z1v.w * w3;
            acc2 += z2v.x * w0 + z2v.y * w1 + z2v.z * w2v + z2v.w * w3;
            acc3 += z3.x * w0 + z3.y * w1 + z3.z * w2v + z3.w * w3;
        }
        sBL[r0 + 0][j] = acc0;
        sBL[r0 + 1][j] = acc1;
        sBL[r0 + 2][j] = acc2;
        sBL[r0 + 3][j] = acc3;
    }
    __syncthreads();

    // ---- P7: beta gumbel top-5 + both PL log-probs ----
    {
        float (*sBL)[64] = (float(*)[64])bufC;
        float mA = sMZ[0], zA = sMZ[1];
#pragma unroll
        for (int k = 0; k < 2; ++k) {
            int r = warp * 2 + k;
            int b = b0 + r;
            float l0 = sBL[r][lane], l1 = sBL[r][lane + 32];
            float u0 = uB[b * 64 + lane];
            float u1 = uB[b * 64 + lane + 32];
            float p0 = l0 - logf(-logf(fmaxf(u0, 1e-10f)));
            float p1 = l1 - logf(-logf(fmaxf(u1, 1e-10f)));
            int sel[5];
            warp_top5(p0, p1, lane, sel);
            float m = fmaxf(l0, l1);
#pragma unroll
            for (int off = 16; off; off >>= 1) m = fmaxf(m, __shfl_xor_sync(0xffffffffu, m, off));
            float z = __expf(l0 - m) + __expf(l1 - m);
#pragma unroll
            for (int off = 16; off; off >>= 1) z += __shfl_xor_sync(0xffffffffu, z, off);
            if (lane == 0) {
                sSelB[r][0] = sel[0]; sSelB[r][1] = sel[1]; sSelB[r][2] = sel[2];
                sSelB[r][3] = sel[3]; sSelB[r][4] = sel[4];
                float eb[5], Sb = 0.0f;
#pragma unroll
                for (int q = 0; q < 5; ++q) {
                    float lv = sBL[r][sel[q]];
                    Sb += lv;
                    eb[q] = __expf(lv - m);
                }
                float lpb = pl_lp(eb, Sb, m, z);
                float ea[5], Sa = 0.0f;
#pragma unroll
                for (int q = 0; q < 5; ++q) {
                    int ia = sSelA[r][q];
                    Sa += sAL[ia];
                    ea[q] = sExpA[ia];
                }
                float lpa = pl_lp(ea, Sa, mA, zA);
                out[Btot * 128 + b] = lpa + lpb;
            }
        }
    }
    __syncthreads();

    // ---- P8: write configs (0/1 masks) ----
    {
#pragma unroll
        for (int e = 0; e < 8; ++e) {
            int idx = t + NTHR * e;
            int r = idx >> 7, j = idx & 127;
            int b = b0 + r;
            float v;
            if (j < 64) {
                const int* s = sSelA[r];
                v = (j == s[0] || j == s[1] || j == s[2] || j == s[3] || j == s[4]) ? 1.0f : 0.0f;
            } else {
                int jj = j - 64;
                const int* s = sSelB[r];
                v = (jj == s[0] || jj == s[1] || jj == s[2] || jj == s[3] || jj == s[4]) ? 1.0f : 0.0f;
            }
            out[b * 128 + j] = v;
        }
    }
}

extern "C" void kernel_launch(void* const* d_in, const int* in_sizes, int n_in,
                              void* d_out, int out_size) {
    const float* uA = (const float*)d_in[0];
    const float* uB = (const float*)d_in[1];
    const float* aL = (const float*)d_in[2];
    const float* W1 = (const float*)d_in[3];
    const float* b1 = (const float*)d_in[4];
    const float* W2 = (const float*)d_in[5];
    const float* b2 = (const float*)d_in[6];
    const float* V1 = (const float*)d_in[7];
    const float* c1 = (const float*)d_in[8];
    const float* V2 = (const float*)d_in[9];
    const float* c2 = (const float*)d_in[10];
    const float* V3 = (const float*)d_in[11];
    const float* c3 = (const float*)d_in[12];
    int B = in_sizes[0] / 64;
    int grid = B / ROWS;
    pcf_kernel<<<grid, NTHR>>>(uA, uB, aL, W1, b1, W2, b2,
                               V1, c1, V2, c2, V3, c3,
                               (float*)d_out, B);
}

// round 4
// speedup vs baseline: 1.5581x; 1.2503x over previous
#include <cuda_runtime.h>
#include <math.h>

#define ROWS 32
#define NTHR 256

__device__ __forceinline__ float siluf(float x) {
    return x / (1.0f + __expf(-x));
}

// Exact Plackett-Luce log-prob of an unordered 5-set via subset DP.
__device__ __forceinline__ float pl_lp(const float e[5], float S, float m, float Z) {
    float g[32];
    float sE[32];
    g[0] = 1.0f;
    sE[0] = 0.0f;
#pragma unroll
    for (int mask = 1; mask < 32; ++mask) {
        float se = 0.0f;
        float acc = 0.0f;
#pragma unroll
        for (int i = 0; i < 5; ++i) {
            if (mask & (1 << i)) {
                int sub = mask ^ (1 << i);
                se += e[i];
                acc += g[sub] * __fdividef(1.0f, Z - sE[sub]);
            }
        }
        sE[mask] = se;
        g[mask] = acc;
    }
    return S - 5.0f * m + logf(g[31]);
}

// Warp-collective top-5 over 64 values (2 per lane). Tie-break: smaller index.
__device__ __forceinline__ void warp_top5(float v0, float v1, int lane, int sel[5]) {
    int i0 = lane, i1 = lane + 32;
#pragma unroll
    for (int q = 0; q < 5; ++q) {
        float bv; int bi;
        if (v0 > v1 || (v0 == v1 && i0 < i1)) { bv = v0; bi = i0; }
        else { bv = v1; bi = i1; }
#pragma unroll
        for (int off = 16; off > 0; off >>= 1) {
            float ov = __shfl_xor_sync(0xffffffffu, bv, off);
            int   oi = __shfl_xor_sync(0xffffffffu, bi, off);
            if (ov > bv || (ov == bv && oi < bi)) { bv = ov; bi = oi; }
        }
        sel[q] = bi;
        if (bi == i0) v0 = -INFINITY;
        if (bi == i1) v1 = -INFINITY;
    }
}

__global__ void __launch_bounds__(NTHR, 2) pcf_kernel(
    const float* __restrict__ uA, const float* __restrict__ uB,
    const float* __restrict__ aLog,
    const float* __restrict__ W1, const float* __restrict__ b1,
    const float* __restrict__ W2, const float* __restrict__ b2,
    const float* __restrict__ V1, const float* __restrict__ c1,
    const float* __restrict__ V2, const float* __restrict__ c2,
    const float* __restrict__ V3, const float* __restrict__ c3,
    float* __restrict__ out, int Btot)
{
    __shared__ float sAL[64];
    __shared__ float sExpA[64];
    __shared__ float sMZ[2];
    __shared__ int   sSelA[ROWS][5];
    __shared__ int   sSelB[ROWS][5];
    __shared__ __align__(16) float bufA[ROWS * 256]; // H [32][128] then Z2 [32][256]
    __shared__ __align__(16) float bufB[ROWS * 256]; // Z1 [32][256]
    __shared__ __align__(16) float bufC[ROWS * 64];  // Ctx [32][64] then BL [32][64]

    const int t = threadIdx.x;
    const int lane = t & 31;
    const int warp = t >> 5;
    const int b0 = blockIdx.x * ROWS;

    if (t < 64) sAL[t] = aLog[t];
    __syncthreads();

    // ---- P1: alpha softmax stats (warp 0) + alpha gumbel top-5 (4 rows/warp) ----
    if (warp == 0) {
        float l0 = sAL[lane], l1 = sAL[lane + 32];
        float m = fmaxf(l0, l1);
#pragma unroll
        for (int off = 16; off; off >>= 1) m = fmaxf(m, __shfl_xor_sync(0xffffffffu, m, off));
        float e0 = __expf(l0 - m), e1 = __expf(l1 - m);
        sExpA[lane] = e0; sExpA[lane + 32] = e1;
        float z = e0 + e1;
#pragma unroll
        for (int off = 16; off; off >>= 1) z += __shfl_xor_sync(0xffffffffu, z, off);
        if (lane == 0) { sMZ[0] = m; sMZ[1] = z; }
    }
    {
        float l0 = sAL[lane], l1 = sAL[lane + 32];
#pragma unroll
        for (int k = 0; k < 4; ++k) {
            int r = warp * 4 + k;
            int b = b0 + r;
            float u0 = uA[b * 64 + lane];
            float u1 = uA[b * 64 + lane + 32];
            float p0 = l0 - logf(-logf(fmaxf(u0, 1e-10f)));
            float p1 = l1 - logf(-logf(fmaxf(u1, 1e-10f)));
            int sel[5];
            warp_top5(p0, p1, lane, sel);
            if (lane == 0) {
                sSelA[r][0] = sel[0]; sSelA[r][1] = sel[1]; sSelA[r][2] = sel[2];
                sSelA[r][3] = sel[3]; sSelA[r][4] = sel[4];
            }
        }
    }
    __syncthreads();

    // ---- P2: h = silu(gather-sum of 5 W1 rows + b1)  [32][128] ----
    {
        float (*sH)[128] = (float(*)[128])bufA;
#pragma unroll
        for (int e = 0; e < 16; ++e) {
            int idx = t + NTHR * e;
            int r = idx >> 7, j = idx & 127;
            const int* sel = sSelA[r];
            float s = b1[j];
#pragma unroll
            for (int q = 0; q < 5; ++q) s += W1[sel[q] * 128 + j];
            sH[r][j] = siluf(s);
        }
    }
    __syncthreads();

    // ---- P3: ctx = h @ W2 + b2   [32][64]  (8 rows x 1 col per thread) ----
    {
        float (*sH)[128] = (float(*)[128])bufA;
        float (*sCtx)[64] = (float(*)[64])bufC;
        const int j = t & 63;
        const int r0 = (t >> 6) * 8;
        float acc[8];
        float bj = b2[j];
#pragma unroll
        for (int r = 0; r < 8; ++r) acc[r] = bj;
#pragma unroll 4
        for (int kc = 0; kc < 32; ++kc) {
            float w0 = W2[(kc * 4 + 0) * 64 + j];
            float w1 = W2[(kc * 4 + 1) * 64 + j];
            float w2v = W2[(kc * 4 + 2) * 64 + j];
            float w3 = W2[(kc * 4 + 3) * 64 + j];
#pragma unroll
            for (int r = 0; r < 8; ++r) {
                float4 h = *(const float4*)&sH[r0 + r][kc * 4];
                acc[r] += h.x * w0 + h.y * w1 + h.z * w2v + h.w * w3;
            }
        }
#pragma unroll
        for (int r = 0; r < 8; ++r) sCtx[r0 + r][j] = acc[r];
    }
    __syncthreads();

    // ---- P4: z1 = silu(ctx @ V1[64:,:] + c1)  [32][256]  (8x4 tile) ----
    {
        float (*sCtx)[64] = (float(*)[64])bufC;
        float (*sZ1)[256] = (float(*)[256])bufB;
        const int j0 = (t & 63) * 4;
        const int r0 = (t >> 6) * 8;
        float4 bias = *(const float4*)&c1[j0];
        float acc[8][4];
#pragma unroll
        for (int r = 0; r < 8; ++r) {
            acc[r][0] = bias.x; acc[r][1] = bias.y; acc[r][2] = bias.z; acc[r][3] = bias.w;
        }
#pragma unroll 2
        for (int kc = 0; kc < 16; ++kc) {
            float4 w[4];
#pragma unroll
            for (int i = 0; i < 4; ++i)
                w[i] = *(const float4*)&V1[(64 + kc * 4 + i) * 256 + j0];
#pragma unroll
            for (int r = 0; r < 8; ++r) {
                float4 z = *(const float4*)&sCtx[r0 + r][kc * 4];
                acc[r][0] += z.x * w[0].x + z.y * w[1].x + z.z * w[2].x + z.w * w[3].x;
                acc[r][1] += z.x * w[0].y + z.y * w[1].y + z.z * w[2].y + z.w * w[3].y;
                acc[r][2] += z.x * w[0].z + z.y * w[1].z + z.z * w[2].z + z.w * w[3].z;
                acc[r][3] += z.x * w[0].w + z.y * w[1].w + z.z * w[2].w + z.w * w[3].w;
            }
        }
#pragma unroll
        for (int r = 0; r < 8; ++r) {
            float4 o;
            o.x = siluf(acc[r][0]); o.y = siluf(acc[r][1]);
            o.z = siluf(acc[r][2]); o.w = siluf(acc[r][3]);
            *(float4*)&sZ1[r0 + r][j0] = o;
        }
    }
    __syncthreads();

    // ---- P5: z2 = silu(z1 @ V2 + c2)  [32][256]  (8x4 tile, dominant) ----
    {
        float (*sZ1)[256] = (float(*)[256])bufB;
        float (*sZ2)[256] = (float(*)[256])bufA;
        const int j0 = (t & 63) * 4;
        const int r0 = (t >> 6) * 8;
        float4 bias = *(const float4*)&c2[j0];
        float acc[8][4];
#pragma unroll
        for (int r = 0; r < 8; ++r) {
            acc[r][0] = bias.x; acc[r][1] = bias.y; acc[r][2] = bias.z; acc[r][3] = bias.w;
        }
#pragma unroll 2
        for (int kc = 0; kc < 64; ++kc) {
            float4 w[4];
#pragma unroll
            for (int i = 0; i < 4; ++i)
                w[i] = *(const float4*)&V2[(kc * 4 + i) * 256 + j0];
#pragma unroll
            for (int r = 0; r < 8; ++r) {
                float4 z = *(const float4*)&sZ1[r0 + r][kc * 4];
                acc[r][0] += z.x * w[0].x + z.y * w[1].x + z.z * w[2].x + z.w * w[3].x;
                acc[r][1] += z.x * w[0].y + z.y * w[1].y + z.z * w[2].y + z.w * w[3].y;
                acc[r][2] += z.x * w[0].z + z.y * w[1].z + z.z * w[2].z + z.w * w[3].z;
                acc[r][3] += z.x * w[0].w + z.y * w[1].w + z.z * w[2].w + z.w * w[3].w;
            }
        }
#pragma unroll
        for (int r = 0; r < 8; ++r) {
            float4 o;
            o.x = siluf(acc[r][0]); o.y = siluf(acc[r][1]);
            o.z = siluf(acc[r][2]); o.w = siluf(acc[r][3]);
            *(float4*)&sZ2[r0 + r][j0] = o;
        }
    }
    __syncthreads();

    // ---- P6: beta_logits = z2 @ V3 + c3  [32][64]  (8 rows x 1 col) ----
    {
        float (*sZ2)[256] = (float(*)[256])bufA;
        float (*sBL)[64] = (float(*)[64])bufC;
        const int j = t & 63;
        const int r0 = (t >> 6) * 8;
        float acc[8];
        float cj = c3[j];
#pragma unroll
        for (int r = 0; r < 8; ++r) acc[r] = cj;
#pragma unroll 4
        for (int kc = 0; kc < 64; ++kc) {
            float w0 = V3[(kc * 4 + 0) * 64 + j];
            float w1 = V3[(kc * 4 + 1) * 64 + j];
            float w2v = V3[(kc * 4 + 2) * 64 + j];
            float w3 = V3[(kc * 4 + 3) * 64 + j];
#pragma unroll
            for (int r = 0; r < 8; ++r) {
                float4 z = *(const float4*)&sZ2[r0 + r][kc * 4];
                acc[r] += z.x * w0 + z.y * w1 + z.z * w2v + z.w * w3;
            }
        }
#pragma unroll
        for (int r = 0; r < 8; ++r) sBL[r0 + r][j] = acc[r];
    }
    __syncthreads();

    // ---- P7: beta gumbel top-5 + both PL log-probs (4 rows/warp) ----
    {
        float (*sBL)[64] = (float(*)[64])bufC;
        float mA = sMZ[0], zA = sMZ[1];
#pragma unroll
        for (int k = 0; k < 4; ++k) {
            int r = warp * 4 + k;
            int b = b0 + r;
            float l0 = sBL[r][lane], l1 = sBL[r][lane + 32];
            float u0 = uB[b * 64 + lane];
            float u1 = uB[b * 64 + lane + 32];
            float p0 = l0 - logf(-logf(fmaxf(u0, 1e-10f)));
            float p1 = l1 - logf(-logf(fmaxf(u1, 1e-10f)));
            int sel[5];
            warp_top5(p0, p1, lane, sel);
            float m = fmaxf(l0, l1);
#pragma unroll
            for (int off = 16; off; off >>= 1) m = fmaxf(m, __shfl_xor_sync(0xffffffffu, m, off));
            float z = __expf(l0 - m) + __expf(l1 - m);
#pragma unroll
            for (int off = 16; off; off >>= 1) z += __shfl_xor_sync(0xffffffffu, z, off);
            if (lane == 0) {
                sSelB[r][0] = sel[0]; sSelB[r][1] = sel[1]; sSelB[r][2] = sel[2];
                sSelB[r][3] = sel[3]; sSelB[r][4] = sel[4];
                float eb[5], Sb = 0.0f;
#pragma unroll
                for (int q = 0; q < 5; ++q) {
                    float lv = sBL[r][sel[q]];
                    Sb += lv;
                    eb[q] = __expf(lv - m);
                }
                float lpb = pl_lp(eb, Sb, m, z);
                float ea[5], Sa = 0.0f;
#pragma unroll
                for (int q = 0; q < 5; ++q) {
                    int ia = sSelA[r][q];
                    Sa += sAL[ia];
                    ea[q] = sExpA[ia];
                }
                float lpa = pl_lp(ea, Sa, mA, zA);
                out[Btot * 128 + b] = lpa + lpb;
            }
        }
    }
    __syncthreads();

    // ---- P8: write configs (0/1 masks) ----
    {
#pragma unroll
        for (int e = 0; e < 16; ++e) {
            int idx = t + NTHR * e;
            int r = idx >> 7, j = idx & 127;
            int b = b0 + r;
            float v;
            if (j < 64) {
                const int* s = sSelA[r];
                v = (j == s[0] || j == s[1] || j == s[2] || j == s[3] || j == s[4]) ? 1.0f : 0.0f;
            } else {
                int jj = j - 64;
                const int* s = sSelB[r];
                v = (jj == s[0] || jj == s[1] || jj == s[2] || jj == s[3] || jj == s[4]) ? 1.0f : 0.0f;
            }
            out[b * 128 + j] = v;
        }
    }
}

extern "C" void kernel_launch(void* const* d_in, const int* in_sizes, int n_in,
                              void* d_out, int out_size) {
    const float* uA = (const float*)d_in[0];
    const float* uB = (const float*)d_in[1];
    const float* aL = (const float*)d_in[2];
    const float* W1 = (const float*)d_in[3];
    const float* b1 = (const float*)d_in[4];
    const float* W2 = (const float*)d_in[5];
    const float* b2 = (const float*)d_in[6];
    const float* V1 = (const float*)d_in[7];
    const float* c1 = (const float*)d_in[8];
    const float* V2 = (const float*)d_in[9];
    const float* c2 = (const float*)d_in[10];
    const float* V3 = (const float*)d_in[11];
    const float* c3 = (const float*)d_in[12];
    int B = in_sizes[0] / 64;
    int grid = B / ROWS;
    pcf_kernel<<<grid, NTHR>>>(uA, uB, aL, W1, b1, W2, b2,
                               V1, c1, V2, c2, V3, c3,
                               (float*)d_out, B);
}